// round 3
// baseline (speedup 1.0000x reference)
#include <cuda_runtime.h>
#include <cuda_bf16.h>
#include <cstdint>

// costs[0,i,j] = 0.5*(|x_i|^2 + |y_j|^2) - x_i . y_j
// x: [1,4096,128] f32, y: [1,4096,128] f32, out: [1,4096,4096] f32.
//
// compute_103 virtual arch => no tcgen05. Use classic mma.sync tf32 HMMA
// (sm_80 baseline), single pass, cvt.rna rounding, fragment-major smem.

#define NROWS 4096
#define DK    128
#define TILE  128

static __device__ float g_x2[NROWS];
static __device__ float g_y2[NROWS];

// ---- helpers ----
__device__ __forceinline__ float to_tf32(float f) {
    uint32_t u;
    asm("cvt.rna.tf32.f32 %0, %1;" : "=r"(u) : "f"(f));
    return __uint_as_float(u);
}

__device__ __forceinline__ void mma8(float* d, const float4& a, const float2& b) {
    asm volatile(
        "mma.sync.aligned.m16n8k8.row.col.f32.tf32.tf32.f32 "
        "{%0,%1,%2,%3}, {%4,%5,%6,%7}, {%8,%9}, {%0,%1,%2,%3};"
        : "+f"(d[0]), "+f"(d[1]), "+f"(d[2]), "+f"(d[3])
        : "r"(__float_as_uint(a.x)), "r"(__float_as_uint(a.y)),
          "r"(__float_as_uint(a.z)), "r"(__float_as_uint(a.w)),
          "r"(__float_as_uint(b.x)), "r"(__float_as_uint(b.y)));
}

// ---- smem layout (floats) ----
// ys:    128 floats                     @ 0
// A_frag [8 m_tiles][16 k_steps][132]   @ 128         (pad 132 to break bank alias)
// B_frag [16 n_tiles][16 k_steps][68]   @ 128 + 16896
#define AF_STRIDE 132
#define BF_STRIDE 68
#define AF_OFF    128
#define BF_OFF    (128 + 8 * 16 * AF_STRIDE)                 // 17024
#define SM_FLOATS (BF_OFF + 16 * 16 * BF_STRIDE)             // 17024 + 17408 = 34432
#define SM_TOTAL  (SM_FLOATS * 4)                            // 137728 bytes

// ---- pre-kernel: exact fp32 row norms ----
__global__ void rownorm_kernel(const float* __restrict__ x, const float* __restrict__ y) {
    int i = blockIdx.x * blockDim.x + threadIdx.x;   // 0..8191
    const float4* p = (const float4*)(i < NROWS ? x + (size_t)i * DK
                                                : y + (size_t)(i - NROWS) * DK);
    float s = 0.f;
#pragma unroll
    for (int j = 0; j < DK / 4; j++) {
        float4 v = p[j];
        s += v.x * v.x + v.y * v.y + v.z * v.z + v.w * v.w;
    }
    if (i < NROWS) g_x2[i] = s; else g_y2[i - NROWS] = s;
}

// ---- main kernel: 128x128 tile per CTA, K=128 one-shot, 8 warps (4M x 2N) ----
__global__ void __launch_bounds__(256, 1)
cost_kernel(const float* __restrict__ x, const float* __restrict__ y, float* __restrict__ out) {
    extern __shared__ float smem[];
    float* ys = smem;
    float* Af = smem + AF_OFF;
    float* Bf = smem + BF_OFF;

    const int tid = threadIdx.x;
    const int wid = tid >> 5;
    const int lane = tid & 31;

    const int m0 = blockIdx.y * TILE;
    const int n0 = blockIdx.x * TILE;

    if (tid < 128) ys[tid] = 0.5f * g_y2[n0 + tid];

    // Fill fragment-major smem tiles. Each thread: 16 float4 loads from x and y.
    // Element (row, k): A frag lane = (row%8)*4 + (k%4), reg = (row%16>=8) + 2*((k%8)>=4)
    //                   B frag lane = (row%8)*4 + (k%4), reg = ((k%8)>=4)
#pragma unroll 4
    for (int it = 0; it < 16; it++) {
        int flat = tid + 256 * it;          // 0..4095
        int row  = flat >> 5;               // 0..127
        int q    = flat & 31;
        int k0   = q << 2;                  // 0,4,...,124
        int ks   = k0 >> 3;
        int upper = (k0 & 4) ? 1 : 0;       // (k0%8) >= 4

        // x -> A
        {
            float4 v = *(const float4*)(x + (size_t)(m0 + row) * DK + k0);
            int mt = row >> 4, r = row & 15;
            int regA = ((r >= 8) ? 1 : 0) + 2 * upper;
            int laneA = (r & 7) << 2;
            float* pa = Af + (mt * 16 + ks) * AF_STRIDE + regA;
            pa[(laneA + 0) * 4] = to_tf32(v.x);
            pa[(laneA + 1) * 4] = to_tf32(v.y);
            pa[(laneA + 2) * 4] = to_tf32(v.z);
            pa[(laneA + 3) * 4] = to_tf32(v.w);
        }
        // y -> B
        {
            float4 v = *(const float4*)(y + (size_t)(n0 + row) * DK + k0);
            int nt = row >> 3;
            int laneB = (row & 7) << 2;
            float* pb = Bf + (nt * 16 + ks) * BF_STRIDE + upper;
            pb[(laneB + 0) * 2] = to_tf32(v.x);
            pb[(laneB + 1) * 2] = to_tf32(v.y);
            pb[(laneB + 2) * 2] = to_tf32(v.z);
            pb[(laneB + 3) * 2] = to_tf32(v.w);
        }
    }
    __syncthreads();

    // Warp tiling: w_m in 0..3 (32 rows each), w_n in 0..1 (64 cols each)
    const int w_m = wid & 3, w_n = wid >> 2;

    float acc[2][8][4];
#pragma unroll
    for (int mi = 0; mi < 2; mi++)
#pragma unroll
        for (int j = 0; j < 8; j++)
#pragma unroll
            for (int r = 0; r < 4; r++) acc[mi][j][r] = 0.f;

    const float* Aw0 = Af + (w_m * 2 + 0) * 16 * AF_STRIDE + lane * 4;
    const float* Aw1 = Af + (w_m * 2 + 1) * 16 * AF_STRIDE + lane * 4;
    const float* Bw  = Bf + (w_n * 8) * 16 * BF_STRIDE + lane * 2;

#pragma unroll
    for (int ks = 0; ks < 16; ks++) {
        float4 a0 = *(const float4*)(Aw0 + ks * AF_STRIDE);
        float4 a1 = *(const float4*)(Aw1 + ks * AF_STRIDE);
        float2 b[8];
#pragma unroll
        for (int j = 0; j < 8; j++)
            b[j] = *(const float2*)(Bw + j * 16 * BF_STRIDE + ks * BF_STRIDE);
#pragma unroll
        for (int j = 0; j < 8; j++) {
            mma8(acc[0][j], a0, b[j]);
            mma8(acc[1][j], a1, b[j]);
        }
    }

    // Epilogue: c0,c1 -> (row=gid, cols 2*tig,2*tig+1); c2,c3 -> row gid+8.
    const int gid = lane >> 2, tig = lane & 3;
    const int mrow_base = m0 + w_m * 32;

#pragma unroll
    for (int mi = 0; mi < 2; mi++) {
#pragma unroll
        for (int h = 0; h < 2; h++) {
            const int m = mrow_base + mi * 16 + h * 8 + gid;
            const float xv = 0.5f * g_x2[m];
            float* orow = out + (size_t)m * NROWS + n0 + w_n * 64 + tig * 2;
#pragma unroll
            for (int j = 0; j < 8; j++) {
                const int col = w_n * 64 + j * 8 + tig * 2;
                float2 o;
                o.x = xv + ys[col + 0] - acc[mi][j][h * 2 + 0];
                o.y = xv + ys[col + 1] - acc[mi][j][h * 2 + 1];
                *(float2*)(orow + j * 8) = o;
            }
        }
    }
}

// ---- launch ----
extern "C" void kernel_launch(void* const* d_in, const int* in_sizes, int n_in,
                              void* d_out, int out_size) {
    const float* x = (const float*)d_in[0];
    const float* y = (const float*)d_in[1];
    float* out = (float*)d_out;

    cudaFuncSetAttribute(cost_kernel, cudaFuncAttributeMaxDynamicSharedMemorySize, SM_TOTAL);

    rownorm_kernel<<<(2 * NROWS) / 256, 256>>>(x, y);
    dim3 grid(NROWS / TILE, NROWS / TILE);
    cost_kernel<<<grid, 256, SM_TOTAL>>>(x, y, out);
}

// round 4
// speedup vs baseline: 1.0394x; 1.0394x over previous
#include <cuda_runtime.h>
#include <cuda_bf16.h>
#include <cstdint>

// costs[0,i,j] = 0.5*(|x_i|^2 + |y_j|^2) - x_i . y_j
// x: [1,4096,128] f32, y: [1,4096,128] f32, out: [1,4096,4096] f32.
//
// tf32 mma.sync (compute_103-safe), fragment-major smem, 512 threads,
// 16 warps x (32x32) warp tiles, paired-B packing for LDS.128 feeds.

#define NROWS 4096
#define DK    128
#define TILE  128

static __device__ float g_x2[NROWS];
static __device__ float g_y2[NROWS];

// ---- helpers ----
__device__ __forceinline__ float to_tf32(float f) {
    uint32_t u;
    asm("cvt.rna.tf32.f32 %0, %1;" : "=r"(u) : "f"(f));
    return __uint_as_float(u);
}

__device__ __forceinline__ void mma8(float* d, const float4& a, float b0, float b1) {
    asm volatile(
        "mma.sync.aligned.m16n8k8.row.col.f32.tf32.tf32.f32 "
        "{%0,%1,%2,%3}, {%4,%5,%6,%7}, {%8,%9}, {%0,%1,%2,%3};"
        : "+f"(d[0]), "+f"(d[1]), "+f"(d[2]), "+f"(d[3])
        : "r"(__float_as_uint(a.x)), "r"(__float_as_uint(a.y)),
          "r"(__float_as_uint(a.z)), "r"(__float_as_uint(a.w)),
          "r"(__float_as_uint(b0)), "r"(__float_as_uint(b1)));
}

// ---- smem layout (floats) ----
// ys:  128 floats @ 0
// A_frag [8 m_tiles][16 ks][132]        @ 128        (lane*4 + reg, pad->132)
// B_frag [8 nt_pairs][16 ks][132]       @ 128+16896  (lane*4 + comp, pad->132)
//   comp = (nt&1)*2 + (k%8>=4);  lane slot = (n%8)*4 + (k%4)
#define FR_STRIDE 132
#define AF_OFF    128
#define BF_OFF    (128 + 8 * 16 * FR_STRIDE)        // 17024
#define SM_FLOATS (BF_OFF + 8 * 16 * FR_STRIDE)     // 33920
#define SM_TOTAL  (SM_FLOATS * 4)                   // 135680 bytes

// ---- pre-kernel: exact fp32 row norms ----
__global__ void rownorm_kernel(const float* __restrict__ x, const float* __restrict__ y) {
    int i = blockIdx.x * blockDim.x + threadIdx.x;   // 0..8191
    const float4* p = (const float4*)(i < NROWS ? x + (size_t)i * DK
                                                : y + (size_t)(i - NROWS) * DK);
    float s = 0.f;
#pragma unroll
    for (int j = 0; j < DK / 4; j++) {
        float4 v = p[j];
        s += v.x * v.x + v.y * v.y + v.z * v.z + v.w * v.w;
    }
    if (i < NROWS) g_x2[i] = s; else g_y2[i - NROWS] = s;
}

// ---- main kernel: 128x128 tile/CTA, 16 warps (4M x 4N of 32x32) ----
__global__ void __launch_bounds__(512, 1)
cost_kernel(const float* __restrict__ x, const float* __restrict__ y, float* __restrict__ out) {
    extern __shared__ float smem[];
    float* ys = smem;
    float* Af = smem + AF_OFF;
    float* Bf = smem + BF_OFF;

    const int tid = threadIdx.x;
    const int wid = tid >> 5;
    const int lane = tid & 31;

    const int m0 = blockIdx.y * TILE;
    const int n0 = blockIdx.x * TILE;

    if (tid < 128) ys[tid] = 0.5f * g_y2[n0 + tid];

    // Fill fragment-major smem. 4096 float4 per operand / 512 threads = 8 iters.
#pragma unroll
    for (int it = 0; it < 8; it++) {
        int flat = tid + 512 * it;          // 0..4095
        int row  = flat >> 5;               // 0..127
        int q    = flat & 31;
        int k0   = q << 2;                  // 0,4,...,124
        int ks   = k0 >> 3;
        int upper = (k0 & 4) ? 1 : 0;

        // x -> A: element (row,k): slot=(row%8)*4+(k%4), reg=(row%16>=8)+2*upper
        {
            float4 v = *(const float4*)(x + (size_t)(m0 + row) * DK + k0);
            int mt = row >> 4, r = row & 15;
            int regA = ((r >= 8) ? 1 : 0) + 2 * upper;
            int slot = (r & 7) << 2;
            float* pa = Af + (mt * 16 + ks) * FR_STRIDE + regA;
            pa[(slot + 0) * 4] = to_tf32(v.x);
            pa[(slot + 1) * 4] = to_tf32(v.y);
            pa[(slot + 2) * 4] = to_tf32(v.z);
            pa[(slot + 3) * 4] = to_tf32(v.w);
        }
        // y -> B: nt=row>>3, pair=nt>>1, comp=(nt&1)*2+upper, slot=(row%8)*4+(k%4)
        {
            float4 v = *(const float4*)(y + (size_t)(n0 + row) * DK + k0);
            int nt = row >> 3, pair = nt >> 1;
            int comp = (nt & 1) * 2 + upper;
            int slot = (row & 7) << 2;
            float* pb = Bf + (pair * 16 + ks) * FR_STRIDE + comp;
            pb[(slot + 0) * 4] = to_tf32(v.x);
            pb[(slot + 1) * 4] = to_tf32(v.y);
            pb[(slot + 2) * 4] = to_tf32(v.z);
            pb[(slot + 3) * 4] = to_tf32(v.w);
        }
    }
    __syncthreads();

    // Warp tiling: w_m 0..3 (32 rows), w_n 0..3 (32 cols = 4 n-tiles = 2 pairs)
    const int w_m = wid & 3, w_n = wid >> 2;

    float acc[2][4][4];
#pragma unroll
    for (int mi = 0; mi < 2; mi++)
#pragma unroll
        for (int j = 0; j < 4; j++)
#pragma unroll
            for (int r = 0; r < 4; r++) acc[mi][j][r] = 0.f;

    const float* Aw0 = Af + (w_m * 2 + 0) * 16 * FR_STRIDE + lane * 4;
    const float* Aw1 = Af + (w_m * 2 + 1) * 16 * FR_STRIDE + lane * 4;
    const float* Bw0 = Bf + (w_n * 2 + 0) * 16 * FR_STRIDE + lane * 4;
    const float* Bw1 = Bf + (w_n * 2 + 1) * 16 * FR_STRIDE + lane * 4;

#pragma unroll
    for (int ks = 0; ks < 16; ks++) {
        float4 a0 = *(const float4*)(Aw0 + ks * FR_STRIDE);
        float4 a1 = *(const float4*)(Aw1 + ks * FR_STRIDE);
        float4 b0 = *(const float4*)(Bw0 + ks * FR_STRIDE);
        float4 b1 = *(const float4*)(Bw1 + ks * FR_STRIDE);
        mma8(acc[0][0], a0, b0.x, b0.y);
        mma8(acc[1][0], a1, b0.x, b0.y);
        mma8(acc[0][1], a0, b0.z, b0.w);
        mma8(acc[1][1], a1, b0.z, b0.w);
        mma8(acc[0][2], a0, b1.x, b1.y);
        mma8(acc[1][2], a1, b1.x, b1.y);
        mma8(acc[0][3], a0, b1.z, b1.w);
        mma8(acc[1][3], a1, b1.z, b1.w);
    }

    // Epilogue: acc[mi][j] covers rows w_m*32+mi*16+{0,8}+gid,
    //           cols w_n*32 + j*8 + tig*2 (+1)
    const int gid = lane >> 2, tig = lane & 3;
    const int mrow_base = m0 + w_m * 32;

#pragma unroll
    for (int mi = 0; mi < 2; mi++) {
#pragma unroll
        for (int h = 0; h < 2; h++) {
            const int m = mrow_base + mi * 16 + h * 8 + gid;
            const float xv = 0.5f * g_x2[m];
            float* orow = out + (size_t)m * NROWS + n0 + w_n * 32 + tig * 2;
#pragma unroll
            for (int j = 0; j < 4; j++) {
                const int col = w_n * 32 + j * 8 + tig * 2;
                float2 o;
                o.x = xv + ys[col + 0] - acc[mi][j][h * 2 + 0];
                o.y = xv + ys[col + 1] - acc[mi][j][h * 2 + 1];
                *(float2*)(orow + j * 8) = o;
            }
        }
    }
}

// ---- launch ----
extern "C" void kernel_launch(void* const* d_in, const int* in_sizes, int n_in,
                              void* d_out, int out_size) {
    const float* x = (const float*)d_in[0];
    const float* y = (const float*)d_in[1];
    float* out = (float*)d_out;

    cudaFuncSetAttribute(cost_kernel, cudaFuncAttributeMaxDynamicSharedMemorySize, SM_TOTAL);

    rownorm_kernel<<<(2 * NROWS) / 256, 256>>>(x, y);
    dim3 grid(NROWS / TILE, NROWS / TILE);
    cost_kernel<<<grid, 512, SM_TOTAL>>>(x, y, out);
}

// round 7
// speedup vs baseline: 1.4354x; 1.3810x over previous
#include <cuda_runtime.h>
#include <cuda_bf16.h>
#include <cstdint>

// costs[0,i,j] = 0.5*(|x_i|^2 + |y_j|^2) - x_i . y_j
// x: [1,4096,128] f32, y: [1,4096,128] f32, out: [1,4096,4096] f32.
//
// Single-pass bf16 mma.sync m16n8k16 (compute_103-safe), fragment-major smem,
// 512 threads, 16 warps x (32x32) tiles, 68KB smem -> 2 CTAs/SM for overlap.

#define NROWS 4096
#define DK    128
#define TILE  128

static __device__ float g_x2[NROWS];
static __device__ float g_y2[NROWS];

// ---- helpers ----
// pack {lo=a, hi=b} as bf16x2 (round-nearest)
__device__ __forceinline__ uint32_t pack_bf16x2(float a, float b) {
    uint32_t r;
    asm("cvt.rn.bf16x2.f32 %0, %1, %2;" : "=r"(r) : "f"(b), "f"(a));
    return r;
}

__device__ __forceinline__ void mma16(float* d, const uint4& a, uint32_t b0, uint32_t b1) {
    asm volatile(
        "mma.sync.aligned.m16n8k16.row.col.f32.bf16.bf16.f32 "
        "{%0,%1,%2,%3}, {%4,%5,%6,%7}, {%8,%9}, {%0,%1,%2,%3};"
        : "+f"(d[0]), "+f"(d[1]), "+f"(d[2]), "+f"(d[3])
        : "r"(a.x), "r"(a.y), "r"(a.z), "r"(a.w), "r"(b0), "r"(b1));
}

// ---- smem layout (u32 units) ----
// ys:  128 floats @ 0
// A_frag [8 m_tiles][8 ks][132]  @ 128       (slot*4 + reg, pad 128->132)
// B_frag [8 nt_pairs][8 ks][132] @ 128+8448
#define FR_STRIDE 132
#define AF_OFF    128
#define BF_OFF    (128 + 8 * 8 * FR_STRIDE)          // 8576
#define SM_U32    (BF_OFF + 8 * 8 * FR_STRIDE)       // 17024
#define SM_TOTAL  (SM_U32 * 4)                       // 68096 bytes

// ---- pre-kernel: exact fp32 row norms ----
__global__ void rownorm_kernel(const float* __restrict__ x, const float* __restrict__ y) {
    int i = blockIdx.x * blockDim.x + threadIdx.x;   // 0..8191
    const float4* p = (const float4*)(i < NROWS ? x + (size_t)i * DK
                                                : y + (size_t)(i - NROWS) * DK);
    float s = 0.f;
#pragma unroll
    for (int j = 0; j < DK / 4; j++) {
        float4 v = p[j];
        s += v.x * v.x + v.y * v.y + v.z * v.z + v.w * v.w;
    }
    if (i < NROWS) g_x2[i] = s; else g_y2[i - NROWS] = s;
}

// ---- main kernel: 128x128 tile/CTA, 16 warps (4M x 4N of 32x32), bf16 ----
__global__ void __launch_bounds__(512, 2)
cost_kernel(const float* __restrict__ x, const float* __restrict__ y, float* __restrict__ out) {
    extern __shared__ uint32_t smem[];
    float* ys = (float*)smem;
    uint32_t* Af = smem + AF_OFF;
    uint32_t* Bf = smem + BF_OFF;

    const int tid = threadIdx.x;
    const int wid = tid >> 5;
    const int lane = tid & 31;

    const int m0 = blockIdx.y * TILE;
    const int n0 = blockIdx.x * TILE;

    if (tid < 128) ys[tid] = 0.5f * g_y2[n0 + tid];

    // Fill fragment-major bf16 smem. 4096 float4 per operand / 512 threads = 8 iters.
    // Element (row, k): m16n8k16 A frag reg = (kk>=8)*2 + (row%16>=8),
    //   slot = (row%8)*4 + ((kk>>1)&3), lo-half of bf16x2 = even k.
#pragma unroll
    for (int it = 0; it < 8; it++) {
        int flat = tid + 512 * it;          // 0..4095
        int row  = flat >> 5;               // 0..127
        int q    = flat & 31;
        int k0   = q << 2;                  // 0,4,...,124
        int ks   = k0 >> 4;                 // k-step of 16: 0..7
        int kk0  = k0 & 15;                 // 0,4,8,12
        int tig0 = (kk0 >> 1) & 3;          // 0 or 2
        int hi   = (kk0 >= 8) ? 1 : 0;

        // x -> A
        {
            float4 v = *(const float4*)(x + (size_t)(m0 + row) * DK + k0);
            uint32_t w0 = pack_bf16x2(v.x, v.y);
            uint32_t w1 = pack_bf16x2(v.z, v.w);
            int mt = row >> 4, r15 = row & 15;
            int reg = hi * 2 + ((r15 >= 8) ? 1 : 0);
            int slot = (r15 & 7) * 4 + tig0;
            uint32_t* pa = Af + (mt * 8 + ks) * FR_STRIDE + slot * 4 + reg;
            pa[0] = w0;
            pa[4] = w1;
        }
        // y -> B: pair = nt>>1, comp = (nt&1)*2 + hi, slot = (row%8)*4 + tig
        {
            float4 v = *(const float4*)(y + (size_t)(n0 + row) * DK + k0);
            uint32_t w0 = pack_bf16x2(v.x, v.y);
            uint32_t w1 = pack_bf16x2(v.z, v.w);
            int nt = row >> 3, pair = nt >> 1;
            int comp = (nt & 1) * 2 + hi;
            int slot = (row & 7) * 4 + tig0;
            uint32_t* pb = Bf + (pair * 8 + ks) * FR_STRIDE + slot * 4 + comp;
            pb[0] = w0;
            pb[4] = w1;
        }
    }
    __syncthreads();

    // Warp tiling: w_m 0..3 (32 rows), w_n 0..3 (32 cols = 2 nt-pairs)
    const int w_m = wid & 3, w_n = wid >> 2;

    float acc[2][4][4];
#pragma unroll
    for (int mi = 0; mi < 2; mi++)
#pragma unroll
        for (int j = 0; j < 4; j++)
#pragma unroll
            for (int r = 0; r < 4; r++) acc[mi][j][r] = 0.f;

    const uint32_t* Aw0 = Af + (w_m * 2 + 0) * 8 * FR_STRIDE + lane * 4;
    const uint32_t* Aw1 = Af + (w_m * 2 + 1) * 8 * FR_STRIDE + lane * 4;
    const uint32_t* Bw0 = Bf + (w_n * 2 + 0) * 8 * FR_STRIDE + lane * 4;
    const uint32_t* Bw1 = Bf + (w_n * 2 + 1) * 8 * FR_STRIDE + lane * 4;

#pragma unroll
    for (int ks = 0; ks < 8; ks++) {
        uint4 a0 = *(const uint4*)(Aw0 + ks * FR_STRIDE);
        uint4 a1 = *(const uint4*)(Aw1 + ks * FR_STRIDE);
        uint4 b0 = *(const uint4*)(Bw0 + ks * FR_STRIDE);  // [nt0.b0,nt0.b1,nt1.b0,nt1.b1]
        uint4 b1 = *(const uint4*)(Bw1 + ks * FR_STRIDE);
        mma16(acc[0][0], a0, b0.x, b0.y);
        mma16(acc[1][0], a1, b0.x, b0.y);
        mma16(acc[0][1], a0, b0.z, b0.w);
        mma16(acc[1][1], a1, b0.z, b0.w);
        mma16(acc[0][2], a0, b1.x, b1.y);
        mma16(acc[1][2], a1, b1.x, b1.y);
        mma16(acc[0][3], a0, b1.z, b1.w);
        mma16(acc[1][3], a1, b1.z, b1.w);
    }

    // Epilogue: acc[mi][j] -> rows w_m*32+mi*16+{0,8}+gid, cols w_n*32+j*8+2*tig
    const int gid = lane >> 2, tig = lane & 3;
    const int mrow_base = m0 + w_m * 32;

#pragma unroll
    for (int mi = 0; mi < 2; mi++) {
#pragma unroll
        for (int h = 0; h < 2; h++) {
            const int m = mrow_base + mi * 16 + h * 8 + gid;
            const float xv = 0.5f * g_x2[m];
            float* orow = out + (size_t)m * NROWS + n0 + w_n * 32 + tig * 2;
#pragma unroll
            for (int j = 0; j < 4; j++) {
                const int col = w_n * 32 + j * 8 + tig * 2;
                float2 o;
                o.x = xv + ys[col + 0] - acc[mi][j][h * 2 + 0];
                o.y = xv + ys[col + 1] - acc[mi][j][h * 2 + 1];
                *(float2*)(orow + j * 8) = o;
            }
        }
    }
}

// ---- launch ----
extern "C" void kernel_launch(void* const* d_in, const int* in_sizes, int n_in,
                              void* d_out, int out_size) {
    const float* x = (const float*)d_in[0];
    const float* y = (const float*)d_in[1];
    float* out = (float*)d_out;

    cudaFuncSetAttribute(cost_kernel, cudaFuncAttributeMaxDynamicSharedMemorySize, SM_TOTAL);

    rownorm_kernel<<<(2 * NROWS) / 256, 256>>>(x, y);
    dim3 grid(NROWS / TILE, NROWS / TILE);
    cost_kernel<<<grid, 512, SM_TOTAL>>>(x, y, out);
}

// round 8
// speedup vs baseline: 1.8509x; 1.2895x over previous
#include <cuda_runtime.h>
#include <cuda_bf16.h>
#include <cstdint>

// costs[0,i,j] = 0.5*(|x_i|^2 + |y_j|^2) - x_i . y_j
// x: [1,4096,128] f32, y: [1,4096,128] f32, out: [1,4096,4096] f32.
//
// bf16 mma.sync m16n8k16 + ldmatrix, row-major swizzled smem tiles,
// pre-converted bf16 operands in global scratch, 512 thr, 2 CTAs/SM.

#define NROWS 4096
#define DK    128
#define TILE  128

static __device__ float g_x2[NROWS];
static __device__ float g_y2[NROWS];
static __device__ __align__(16) __nv_bfloat16 g_xb[NROWS * DK];
static __device__ __align__(16) __nv_bfloat16 g_yb[NROWS * DK];

// ---- helpers ----
__device__ __forceinline__ uint32_t pack_bf16x2(float a, float b) {
    uint32_t r;
    asm("cvt.rn.bf16x2.f32 %0, %1, %2;" : "=r"(r) : "f"(b), "f"(a));
    return r;
}

__device__ __forceinline__ uint32_t smem_u32(const void* p) {
    uint32_t a;
    asm("{ .reg .u64 t; cvta.to.shared.u64 t, %1; cvt.u32.u64 %0, t; }" : "=r"(a) : "l"(p));
    return a;
}

__device__ __forceinline__ void ldsm4(uint32_t* r, uint32_t addr) {
    asm volatile("ldmatrix.sync.aligned.m8n8.x4.shared.b16 {%0,%1,%2,%3}, [%4];"
                 : "=r"(r[0]), "=r"(r[1]), "=r"(r[2]), "=r"(r[3]) : "r"(addr));
}

__device__ __forceinline__ void mma16(float* d, const uint32_t* a, uint32_t b0, uint32_t b1) {
    asm volatile(
        "mma.sync.aligned.m16n8k16.row.col.f32.bf16.bf16.f32 "
        "{%0,%1,%2,%3}, {%4,%5,%6,%7}, {%8,%9}, {%0,%1,%2,%3};"
        : "+f"(d[0]), "+f"(d[1]), "+f"(d[2]), "+f"(d[3])
        : "r"(a[0]), "r"(a[1]), "r"(a[2]), "r"(a[3]), "r"(b0), "r"(b1));
}

// ---- smem layout (bytes) ----
// ys (128 f32) @ 0 ; A tile (128x128 bf16, swizzled rows of 256B) @ 512 ;
// B tile @ 512 + 32768. Total 66048 B -> 2 CTAs/SM.
#define SM_YS    0
#define SM_A     512
#define SM_B     (512 + TILE * 256)
#define SM_TOTAL (512 + 2 * TILE * 256)

// swizzled byte offset of 16B-unit (row, cu): row*256 + (cu ^ (row&7))*16

// ---- pre-kernel: row norms + bf16 conversion (one pass) ----
__global__ void prep_kernel(const float* __restrict__ x, const float* __restrict__ y) {
    int gid = blockIdx.x * blockDim.x + threadIdx.x;   // 0 .. 8192*32-1
    int row = gid >> 5;                                 // 0..8191
    int lane = gid & 31;
    bool isx = row < NROWS;
    int r = isx ? row : row - NROWS;
    const float4 v = ((const float4*)(isx ? x : y))[(size_t)r * 32 + lane];
    float s = v.x * v.x + v.y * v.y + v.z * v.z + v.w * v.w;
#pragma unroll
    for (int o = 16; o; o >>= 1) s += __shfl_xor_sync(0xffffffffu, s, o);
    uint2 w;
    w.x = pack_bf16x2(v.x, v.y);
    w.y = pack_bf16x2(v.z, v.w);
    ((uint2*)(isx ? g_xb : g_yb))[(size_t)r * 32 + lane] = w;
    if (lane == 0) { if (isx) g_x2[r] = s; else g_y2[r] = s; }
}

// ---- main kernel: 128x128 tile/CTA, 16 warps (4M x 4N of 32x32) ----
__global__ void __launch_bounds__(512, 2)
cost_kernel(float* __restrict__ out) {
    extern __shared__ char smem[];
    float* ys = (float*)(smem + SM_YS);
    const uint32_t smem_base = smem_u32(smem);

    const int tid = threadIdx.x;
    const int wid = tid >> 5;
    const int lane = tid & 31;

    const int m0 = blockIdx.y * TILE;
    const int n0 = blockIdx.x * TILE;

    if (tid < 128) ys[tid] = 0.5f * g_y2[n0 + tid];

    // Fill: copy 128x128 bf16 tiles (16B units) into swizzled row-major smem.
    // 4096 units total (A: 2048, B: 2048), 512 threads -> 8 iters.
#pragma unroll
    for (int it = 0; it < 8; it++) {
        int flat = tid + 512 * it;                 // 0..4095
        int isB  = flat >> 11;                     // 0: A, 1: B
        int u    = flat & 2047;
        int row  = u >> 4;                         // 0..127
        int cu   = u & 15;                         // 16B-unit within row
        const uint4* src = (const uint4*)(isB ? g_yb : g_xb)
                           + (size_t)((isB ? n0 : m0) + row) * 16 + cu;
        uint4 v = *src;
        char* dst = smem + (isB ? SM_B : SM_A) + row * 256 + ((cu ^ (row & 7)) << 4);
        *(uint4*)dst = v;
    }
    __syncthreads();

    // Warp tiling: w_m 0..3 (32 rows), w_n 0..3 (32 cols)
    const int w_m = wid & 3, w_n = wid >> 2;

    // ldmatrix lane-address precompute.
    // A group: row = mbase + (l%8) + ((l>>3)&1)*8, sel = l>>4
    // B group: row = nbase + (l%8) + (l>>4)*8,     sel = (l>>3)&1
    const int a_row0 = w_m * 32 + (lane & 7) + ((lane >> 3) & 1) * 8;  // mi=0
    const int a_sel  = lane >> 4;
    const int b_row0 = w_n * 32 + (lane & 7) + (lane >> 4) * 8;        // pair=0
    const int b_sel  = (lane >> 3) & 1;

    const uint32_t aBase0 = smem_base + SM_A + a_row0 * 256;
    const uint32_t aBase1 = aBase0 + 16 * 256;
    const uint32_t bBase0 = smem_base + SM_B + b_row0 * 256;
    const uint32_t bBase1 = bBase0 + 16 * 256;
    const int a_ph = a_row0 & 7;
    const int b_ph = b_row0 & 7;

    float acc[2][4][4];
#pragma unroll
    for (int mi = 0; mi < 2; mi++)
#pragma unroll
        for (int j = 0; j < 4; j++)
#pragma unroll
            for (int r = 0; r < 4; r++) acc[mi][j][r] = 0.f;

#pragma unroll
    for (int ks = 0; ks < 8; ks++) {
        const uint32_t aoff = (uint32_t)(((ks * 2 + a_sel) ^ a_ph) << 4);
        const uint32_t boff = (uint32_t)(((ks * 2 + b_sel) ^ b_ph) << 4);
        uint32_t a0[4], a1[4], b0[4], b1[4];
        ldsm4(a0, aBase0 + aoff);   // a-frag rows w_m*32 +  0..15
        ldsm4(a1, aBase1 + aoff);   // a-frag rows w_m*32 + 16..31
        ldsm4(b0, bBase0 + boff);   // {nt0.b0, nt0.b1, nt1.b0, nt1.b1}
        ldsm4(b1, bBase1 + boff);   // {nt2.b0, nt2.b1, nt3.b0, nt3.b1}
        mma16(acc[0][0], a0, b0[0], b0[1]);
        mma16(acc[1][0], a1, b0[0], b0[1]);
        mma16(acc[0][1], a0, b0[2], b0[3]);
        mma16(acc[1][1], a1, b0[2], b0[3]);
        mma16(acc[0][2], a0, b1[0], b1[1]);
        mma16(acc[1][2], a1, b1[0], b1[1]);
        mma16(acc[0][3], a0, b1[2], b1[3]);
        mma16(acc[1][3], a1, b1[2], b1[3]);
    }

    // Epilogue: acc[mi][j] -> rows w_m*32+mi*16+{0,8}+gid, cols w_n*32+j*8+2*tig
    const int gid = lane >> 2, tig = lane & 3;
    const int mrow_base = m0 + w_m * 32;

#pragma unroll
    for (int mi = 0; mi < 2; mi++) {
#pragma unroll
        for (int h = 0; h < 2; h++) {
            const int m = mrow_base + mi * 16 + h * 8 + gid;
            const float xv = 0.5f * g_x2[m];
            float* orow = out + (size_t)m * NROWS + n0 + w_n * 32 + tig * 2;
#pragma unroll
            for (int j = 0; j < 4; j++) {
                const int col = w_n * 32 + j * 8 + tig * 2;
                float2 o;
                o.x = xv + ys[col + 0] - acc[mi][j][h * 2 + 0];
                o.y = xv + ys[col + 1] - acc[mi][j][h * 2 + 1];
                *(float2*)(orow + j * 8) = o;
            }
        }
    }
}

// ---- launch ----
extern "C" void kernel_launch(void* const* d_in, const int* in_sizes, int n_in,
                              void* d_out, int out_size) {
    const float* x = (const float*)d_in[0];
    const float* y = (const float*)d_in[1];
    float* out = (float*)d_out;

    cudaFuncSetAttribute(cost_kernel, cudaFuncAttributeMaxDynamicSharedMemorySize, SM_TOTAL);

    prep_kernel<<<(2 * NROWS * 32) / 256, 256>>>(x, y);
    dim3 grid(NROWS / TILE, NROWS / TILE);
    cost_kernel<<<grid, 512, SM_TOTAL>>>(out);
}

// round 9
// speedup vs baseline: 1.9720x; 1.0654x over previous
#include <cuda_runtime.h>
#include <cuda_bf16.h>
#include <cstdint>

// costs[0,i,j] = 0.5*(|x_i|^2 + |y_j|^2) - x_i . y_j
// x: [1,4096,128] f32, y: [1,4096,128] f32, out: [1,4096,4096] f32.
//
// bf16 mma.sync m16n8k16 + ldmatrix, swizzled row-major smem tiles,
// pre-converted bf16 operands, 256 thr / 8 warps x (64x32) tiles,
// cp.async fill, 2 CTAs/SM.

#define NROWS 4096
#define DK    128
#define TILE  128

static __device__ float g_x2[NROWS];
static __device__ float g_y2[NROWS];
static __device__ __align__(16) __nv_bfloat16 g_xb[NROWS * DK];
static __device__ __align__(16) __nv_bfloat16 g_yb[NROWS * DK];

// ---- helpers ----
__device__ __forceinline__ uint32_t pack_bf16x2(float a, float b) {
    uint32_t r;
    asm("cvt.rn.bf16x2.f32 %0, %1, %2;" : "=r"(r) : "f"(b), "f"(a));
    return r;
}

__device__ __forceinline__ uint32_t smem_u32(const void* p) {
    uint32_t a;
    asm("{ .reg .u64 t; cvta.to.shared.u64 t, %1; cvt.u32.u64 %0, t; }" : "=r"(a) : "l"(p));
    return a;
}

__device__ __forceinline__ void ldsm4(uint32_t* r, uint32_t addr) {
    asm volatile("ldmatrix.sync.aligned.m8n8.x4.shared.b16 {%0,%1,%2,%3}, [%4];"
                 : "=r"(r[0]), "=r"(r[1]), "=r"(r[2]), "=r"(r[3]) : "r"(addr));
}

__device__ __forceinline__ void mma16(float* d, const uint32_t* a, uint32_t b0, uint32_t b1) {
    asm volatile(
        "mma.sync.aligned.m16n8k16.row.col.f32.bf16.bf16.f32 "
        "{%0,%1,%2,%3}, {%4,%5,%6,%7}, {%8,%9}, {%0,%1,%2,%3};"
        : "+f"(d[0]), "+f"(d[1]), "+f"(d[2]), "+f"(d[3])
        : "r"(a[0]), "r"(a[1]), "r"(a[2]), "r"(a[3]), "r"(b0), "r"(b1));
}

__device__ __forceinline__ void cp16(uint32_t dst, const void* src) {
    asm volatile("cp.async.cg.shared.global [%0], [%1], 16;" :: "r"(dst), "l"(src) : "memory");
}

// ---- smem layout (bytes) ----
// ys (128 f32) @ 0 ; A tile (128x128 bf16, swizzled 256B rows) @ 512 ; B @ +32KB.
#define SM_YS    0
#define SM_A     512
#define SM_B     (512 + TILE * 256)
#define SM_TOTAL (512 + 2 * TILE * 256)

// ---- pre-kernel: row norms + bf16 conversion (one pass) ----
__global__ void prep_kernel(const float* __restrict__ x, const float* __restrict__ y) {
    int gid = blockIdx.x * blockDim.x + threadIdx.x;   // 0 .. 8192*32-1
    int row = gid >> 5;
    int lane = gid & 31;
    bool isx = row < NROWS;
    int r = isx ? row : row - NROWS;
    const float4 v = ((const float4*)(isx ? x : y))[(size_t)r * 32 + lane];
    float s = v.x * v.x + v.y * v.y + v.z * v.z + v.w * v.w;
#pragma unroll
    for (int o = 16; o; o >>= 1) s += __shfl_xor_sync(0xffffffffu, s, o);
    uint2 w;
    w.x = pack_bf16x2(v.x, v.y);
    w.y = pack_bf16x2(v.z, v.w);
    ((uint2*)(isx ? g_xb : g_yb))[(size_t)r * 32 + lane] = w;
    if (lane == 0) { if (isx) g_x2[r] = s; else g_y2[r] = s; }
}

// ---- main kernel: 128x128 tile/CTA, 8 warps (2M x 4N of 64x32) ----
__global__ void __launch_bounds__(256, 2)
cost_kernel(float* __restrict__ out) {
    extern __shared__ char smem[];
    float* ys = (float*)(smem + SM_YS);
    const uint32_t smem_base = smem_u32(smem);

    const int tid = threadIdx.x;
    const int wid = tid >> 5;
    const int lane = tid & 31;

    const int m0 = blockIdx.y * TILE;
    const int n0 = blockIdx.x * TILE;

    if (tid < 128) ys[tid] = 0.5f * g_y2[n0 + tid];

    // Fill via cp.async: 4096 16B units (A: 2048, B: 2048), 256 thr -> 16 iters.
#pragma unroll
    for (int it = 0; it < 16; it++) {
        int flat = tid + 256 * it;                 // 0..4095
        int isB  = flat >> 11;
        int u    = flat & 2047;
        int row  = u >> 4;                         // 0..127
        int cu   = u & 15;                         // 16B unit in row
        const uint4* src = (const uint4*)(isB ? g_yb : g_xb)
                           + (size_t)((isB ? n0 : m0) + row) * 16 + cu;
        uint32_t dst = smem_base + (isB ? SM_B : SM_A) + row * 256 + ((cu ^ (row & 7)) << 4);
        cp16(dst, src);
    }
    asm volatile("cp.async.commit_group;" ::: "memory");
    asm volatile("cp.async.wait_group 0;" ::: "memory");
    __syncthreads();

    // Warp tiling: w_m 0..1 (64 rows), w_n 0..3 (32 cols)
    const int w_m = wid >> 2, w_n = wid & 3;

    // ldmatrix lane addressing (same mapping as R8, proven):
    const int a_row0 = w_m * 64 + (lane & 7) + ((lane >> 3) & 1) * 8;
    const int a_sel  = lane >> 4;
    const int b_row0 = w_n * 32 + (lane & 7) + (lane >> 4) * 8;
    const int b_sel  = (lane >> 3) & 1;

    const uint32_t aBase = smem_base + SM_A + a_row0 * 256;   // + ti*16*256
    const uint32_t bBase0 = smem_base + SM_B + b_row0 * 256;
    const uint32_t bBase1 = bBase0 + 16 * 256;
    const int a_ph = a_row0 & 7;
    const int b_ph = b_row0 & 7;

    float acc[4][4][4];
#pragma unroll
    for (int ti = 0; ti < 4; ti++)
#pragma unroll
        for (int j = 0; j < 4; j++)
#pragma unroll
            for (int r = 0; r < 4; r++) acc[ti][j][r] = 0.f;

#pragma unroll
    for (int ks = 0; ks < 8; ks++) {
        const uint32_t aoff = (uint32_t)(((ks * 2 + a_sel) ^ a_ph) << 4);
        const uint32_t boff = (uint32_t)(((ks * 2 + b_sel) ^ b_ph) << 4);
        uint32_t a[4][4], b0[4], b1[4];
        ldsm4(b0, bBase0 + boff);   // {nt0.b0, nt0.b1, nt1.b0, nt1.b1}
        ldsm4(b1, bBase1 + boff);   // {nt2.b0, nt2.b1, nt3.b0, nt3.b1}
#pragma unroll
        for (int ti = 0; ti < 4; ti++)
            ldsm4(a[ti], aBase + ti * (16 * 256) + aoff);
#pragma unroll
        for (int ti = 0; ti < 4; ti++) {
            mma16(acc[ti][0], a[ti], b0[0], b0[1]);
            mma16(acc[ti][1], a[ti], b0[2], b0[3]);
            mma16(acc[ti][2], a[ti], b1[0], b1[1]);
            mma16(acc[ti][3], a[ti], b1[2], b1[3]);
        }
    }

    // Epilogue: acc[ti][j] -> rows w_m*64+ti*16+{0,8}+gid, cols w_n*32+j*8+2*tig
    const int gid = lane >> 2, tig = lane & 3;
    const int mrow_base = m0 + w_m * 64;

#pragma unroll
    for (int ti = 0; ti < 4; ti++) {
#pragma unroll
        for (int h = 0; h < 2; h++) {
            const int m = mrow_base + ti * 16 + h * 8 + gid;
            const float xv = 0.5f * g_x2[m];
            float* orow = out + (size_t)m * NROWS + n0 + w_n * 32 + tig * 2;
#pragma unroll
            for (int j = 0; j < 4; j++) {
                const int col = w_n * 32 + j * 8 + tig * 2;
                float2 o;
                o.x = xv + ys[col + 0] - acc[ti][j][h * 2 + 0];
                o.y = xv + ys[col + 1] - acc[ti][j][h * 2 + 1];
                *(float2*)(orow + j * 8) = o;
            }
        }
    }
}

// ---- launch ----
extern "C" void kernel_launch(void* const* d_in, const int* in_sizes, int n_in,
                              void* d_out, int out_size) {
    const float* x = (const float*)d_in[0];
    const float* y = (const float*)d_in[1];
    float* out = (float*)d_out;

    cudaFuncSetAttribute(cost_kernel, cudaFuncAttributeMaxDynamicSharedMemorySize, SM_TOTAL);

    prep_kernel<<<(2 * NROWS * 32) / 256, 256>>>(x, y);
    dim3 grid(NROWS / TILE, NROWS / TILE);
    cost_kernel<<<grid, 256, SM_TOTAL>>>(out);
}